// round 13
// baseline (speedup 1.0000x reference)
#include <cuda_runtime.h>
#include <math.h>

// B=256 rows, C=2048 features, target groups of 4; output = LAST center's loss.
// Identity: with c = mean of matching rows and R = X X^T,
//   (x_i-c)·(x_j-c) = R_ij - u_i - u_j + cc,  u_i = mean_m R[m,i], cc = mean_m u_m
// so the GEMM runs on RAW inputs; centering/normalization is O(B^2) epilogue.
#define BDIM 256
#define CDIM 2048
#define KB 32                 // k's per smem stage
#define TOTSTG (CDIM / KB)    // 64 stages
#define NSLICE 29             // split-K slices -> 10*29 = 290 CTAs ~ 2/SM, 1 wave
#define NPAIR 10              // upper-triangle 64x64 tile pairs
#define TILE 64
#define LDSR 34               // padded smem row stride: conflict-free LDS.64
#define EPSN 1e-12f

// Scratch (no allocations allowed): per-slice partial Grams + merged Gram.
__device__ float d_Rp[NSLICE][BDIM * BDIM];  // 29 * 256 KB = 7.4 MB
__device__ float d_G[BDIM * BDIM];           // 256 KB

__device__ const int PIT[NPAIR] = {0, 0, 0, 0, 1, 1, 1, 2, 2, 3};
__device__ const int PJT[NPAIR] = {0, 1, 2, 3, 1, 2, 3, 2, 3, 3};

// Packed fp32x2 FMA (sm_10x): 2 fp32 FMA per issue slot on the fma pipe.
__device__ __forceinline__ void ffma2(unsigned long long& d,
                                      unsigned long long a,
                                      unsigned long long b) {
    asm("fma.rn.f32x2 %0, %1, %2, %0;" : "+l"(d) : "l"(a), "l"(b));
}

// ---------------------------------------------------------------------------
// Kernel 1: split-K Gram GEMM on raw X. Grid (NPAIR, NSLICE), 256 threads,
// 2 CTAs/SM. 64x64 tile, 4x4 micro-tile, fp32x2 k-parity accumulators,
// double-buffered smem with register prefetch. Plain STG epilogue into the
// slice's private buffer (+ mirror for off-diagonal tiles).
// ---------------------------------------------------------------------------
__global__ void __launch_bounds__(256, 2) gemm_kernel(const float* __restrict__ x) {
    __shared__ __align__(16) float As[2][TILE * LDSR];
    __shared__ __align__(16) float Bs[2][TILE * LDSR];

    const int tid = threadIdx.x;
    const int tx = tid & 15;       // j-lane (4 j's, strided 16)
    const int ty = tid >> 4;       // i-lane (4 i's, strided 16)
    const int it = PIT[blockIdx.x];
    const int jt = PJT[blockIdx.x];
    const int s  = blockIdx.y;
    const int s0 = (s * TOTSTG) / NSLICE;
    const int s1 = ((s + 1) * TOTSTG) / NSLICE;

    const int lr = tid >> 4;       // loader row-within-16
    const int lk = tid & 15;       // loader k-pair index

    float2 pre[8];
    unsigned long long acc[16];
#pragma unroll
    for (int i = 0; i < 16; i++) acc[i] = 0ull;

    // Stage loader: 64 rows x 32 k per tile = 1024 float2, 4 per thread.
    auto gload = [&](int st) {
        const int kb = st * KB + 2 * lk;
#pragma unroll
        for (int q = 0; q < 4; q++) {
            pre[q]     = *(const float2*)(x + (it * TILE + lr + 16 * q) * CDIM + kb);
            pre[4 + q] = *(const float2*)(x + (jt * TILE + lr + 16 * q) * CDIM + kb);
        }
    };
    auto sstore = [&](int b) {
#pragma unroll
        for (int q = 0; q < 4; q++) {
            *(float2*)(&As[b][(lr + 16 * q) * LDSR + 2 * lk]) = pre[q];
            *(float2*)(&Bs[b][(lr + 16 * q) * LDSR + 2 * lk]) = pre[4 + q];
        }
    };

    gload(s0);
    sstore(0);
    __syncthreads();

    for (int st = s0; st < s1; st++) {
        const int b = (st - s0) & 1;
        if (st + 1 < s1) gload(st + 1);   // prefetch next stage into regs

        const float* Ap = As[b];
        const float* Bp = Bs[b];
#pragma unroll
        for (int kp = 0; kp < KB / 2; kp++) {
            unsigned long long af[4], bf[4];
#pragma unroll
            for (int ii = 0; ii < 4; ii++)
                af[ii] = *(const unsigned long long*)(Ap + (ty + 16 * ii) * LDSR + 2 * kp);
#pragma unroll
            for (int jj = 0; jj < 4; jj++)
                bf[jj] = *(const unsigned long long*)(Bp + (tx + 16 * jj) * LDSR + 2 * kp);
#pragma unroll
            for (int ii = 0; ii < 4; ii++)
#pragma unroll
                for (int jj = 0; jj < 4; jj++)
                    ffma2(acc[ii * 4 + jj], af[ii], bf[jj]);
        }

        if (st + 1 < s1) sstore(b ^ 1);
        __syncthreads();
    }

    float* __restrict__ R = d_Rp[s];
#pragma unroll
    for (int ii = 0; ii < 4; ii++)
#pragma unroll
        for (int jj = 0; jj < 4; jj++) {
            const unsigned long long u = acc[ii * 4 + jj];
            const float r = __uint_as_float((unsigned)u) +
                            __uint_as_float((unsigned)(u >> 32));
            const int gi = it * TILE + ty + 16 * ii;
            const int gj = jt * TILE + tx + 16 * jj;
            R[gi * BDIM + gj] = r;
            if (it != jt) R[gj * BDIM + gi] = r;
        }
}

// ---------------------------------------------------------------------------
// Kernel 2: merge the 29 slices into d_G. 64 blocks x 256 threads, one
// float4 per thread, 29 independent L2-hot loads each. Also zeroes *out.
// ---------------------------------------------------------------------------
__global__ void __launch_bounds__(256) merge_kernel(float* __restrict__ out) {
    const int idx = blockIdx.x * 256 + threadIdx.x;   // float4 index
    float4 v = make_float4(0.f, 0.f, 0.f, 0.f);
#pragma unroll
    for (int s = 0; s < NSLICE; s++) {
        const float4 p = *(const float4*)(&d_Rp[s][idx * 4]);
        v.x += p.x; v.y += p.y; v.z += p.z; v.w += p.w;
    }
    *(float4*)(&d_G[idx * 4]) = v;
    if (idx == 0) *out = 0.f;   // d_out is poisoned each replay
}

// ---------------------------------------------------------------------------
// Kernel 3: centering/normalization corrections + masked min/max + sum.
// 32 blocks x 256 threads, one warp per row; all reads L2-hot.
// ---------------------------------------------------------------------------
__global__ void __launch_bounds__(256) reduce_kernel(const int* __restrict__ tg,
                                                     float* __restrict__ out) {
    __shared__ int mlist[BDIM];
    __shared__ int mcount;
    __shared__ float su[BDIM];
    __shared__ float sinv[BDIM];

    const int tid = threadIdx.x;
    if (tid == 0) mcount = 0;
    __syncthreads();
    const int t_last = tg[BDIM - 4];   // targets[::4][-1]
    if (tg[tid] == t_last) {
        int p = atomicAdd(&mcount, 1);
        mlist[p] = tid;
    }
    __syncthreads();
    const int cnt = mcount;
    const float invc = 1.f / (float)cnt;

    float u = 0.f;
    for (int m = 0; m < cnt; m++) u += d_G[mlist[m] * BDIM + tid];
    u *= invc;
    su[tid] = u;
    const float dg = d_G[tid * (BDIM + 1)];
    __syncthreads();

    float cc = 0.f;
    for (int m = 0; m < cnt; m++) cc += su[mlist[m]];
    cc *= invc;

    const float wii = dg - 2.f * u + cc;   // ||x_tid - c||^2
    sinv[tid] = 1.f / fmaxf(sqrtf(fmaxf(wii, 0.f)), EPSN);
    __syncthreads();

    const int row = blockIdx.x * 8 + (tid >> 5);
    const int lane = tid & 31;
    const int trow = tg[row];
    const float ui = su[row];
    const float invi = sinv[row];
    const float INF = __int_as_float(0x7f800000);

    float pos = INF;
    float neg = 0.f;
#pragma unroll
    for (int jj = 0; jj < 8; jj++) {
        const int j = lane + 32 * jj;
        const float w = d_G[row * BDIM + j] - ui - su[j] + cc;
        const float ang = w * invi * sinv[j];
        const bool same = (tg[j] == trow);
        pos = fminf(pos, same ? ang : INF);
        neg = fmaxf(neg, same ? 0.f : fmaxf(ang, 0.f));
    }
#pragma unroll
    for (int o = 16; o; o >>= 1) {
        pos = fminf(pos, __shfl_xor_sync(0xffffffffu, pos, o));
        neg = fmaxf(neg, __shfl_xor_sync(0xffffffffu, neg, o));
    }
    if (lane == 0) atomicAdd(out, expf(neg - pos) * (1.f / 448.f));
}

// ---------------------------------------------------------------------------
extern "C" void kernel_launch(void* const* d_in, const int* in_sizes, int n_in,
                              void* d_out, int out_size) {
    const float* x  = (const float*)d_in[0];   // inputs  [256, 2048] fp32
    const int*   tg = (const int*)d_in[1];     // targets [256] int32
    // d_in[2] (subs) is unused by the reference math.
    float* out = (float*)d_out;                // scalar fp32

    gemm_kernel<<<dim3(NPAIR, NSLICE), 256>>>(x);
    merge_kernel<<<BDIM * BDIM / 4 / 256, 256>>>(out);
    reduce_kernel<<<BDIM / 8, 256>>>(tg, out);
}

// round 14
// speedup vs baseline: 1.0015x; 1.0015x over previous
#include <cuda_runtime.h>
#include <math.h>

// B=256 rows, C=2048 features, target groups of 4; output = LAST center's loss.
// Identity: with c = mean of matching rows and R = X X^T,
//   (x_i-c)·(x_j-c) = R_ij - u_i - u_j + cc,  u_i = mean_m R[m,i], cc = mean_m u_m
// so the GEMM runs on RAW inputs; centering/normalization is O(B^2) epilogue.
#define BDIM 256
#define CDIM 2048
#define KB 32                 // k's per smem stage
#define TOTSTG (CDIM / KB)    // 64 stages
#define NSLICE 29             // split-K slices -> 10*29 = 290 CTAs ~ 2/SM, 1 wave
#define NPAIR 10              // upper-triangle 64x64 tile pairs
#define TILE 64
#define LDSR 34               // padded smem row stride: conflict-free LDS.64
#define EPSN 1e-12f

// Scratch (no allocations allowed): per-slice partial Grams + merged Gram.
__device__ float d_Rp[NSLICE][BDIM * BDIM];  // 29 * 256 KB = 7.4 MB
__device__ float d_G[BDIM * BDIM];           // 256 KB

__device__ const int PIT[NPAIR] = {0, 0, 0, 0, 1, 1, 1, 2, 2, 3};
__device__ const int PJT[NPAIR] = {0, 1, 2, 3, 1, 2, 3, 2, 3, 3};

// Packed fp32x2 FMA (sm_10x): 2 fp32 FMA per issue slot on the fma pipe.
__device__ __forceinline__ void ffma2(unsigned long long& d,
                                      unsigned long long a,
                                      unsigned long long b) {
    asm("fma.rn.f32x2 %0, %1, %2, %0;" : "+l"(d) : "l"(a), "l"(b));
}

// ---------------------------------------------------------------------------
// Kernel 1: split-K Gram GEMM on raw X. Grid (NPAIR, NSLICE), 256 threads,
// 2 CTAs/SM. 64x64 tile, 4x4 micro-tile, fp32x2 k-parity accumulators,
// double-buffered smem with register prefetch. Plain STG epilogue into the
// slice's private buffer (+ mirror for off-diagonal tiles).
// ---------------------------------------------------------------------------
__global__ void __launch_bounds__(256, 2) gemm_kernel(const float* __restrict__ x) {
    __shared__ __align__(16) float As[2][TILE * LDSR];
    __shared__ __align__(16) float Bs[2][TILE * LDSR];

    const int tid = threadIdx.x;
    const int tx = tid & 15;       // j-lane (4 j's, strided 16)
    const int ty = tid >> 4;       // i-lane (4 i's, strided 16)
    const int it = PIT[blockIdx.x];
    const int jt = PJT[blockIdx.x];
    const int s  = blockIdx.y;
    const int s0 = (s * TOTSTG) / NSLICE;
    const int s1 = ((s + 1) * TOTSTG) / NSLICE;

    const int lr = tid >> 4;       // loader row-within-16
    const int lk = tid & 15;       // loader k-pair index

    float2 pre[8];
    unsigned long long acc[16];
#pragma unroll
    for (int i = 0; i < 16; i++) acc[i] = 0ull;

    // Stage loader: 64 rows x 32 k per tile = 1024 float2, 4 per thread.
    auto gload = [&](int st) {
        const int kb = st * KB + 2 * lk;
#pragma unroll
        for (int q = 0; q < 4; q++) {
            pre[q]     = *(const float2*)(x + (it * TILE + lr + 16 * q) * CDIM + kb);
            pre[4 + q] = *(const float2*)(x + (jt * TILE + lr + 16 * q) * CDIM + kb);
        }
    };
    auto sstore = [&](int b) {
#pragma unroll
        for (int q = 0; q < 4; q++) {
            *(float2*)(&As[b][(lr + 16 * q) * LDSR + 2 * lk]) = pre[q];
            *(float2*)(&Bs[b][(lr + 16 * q) * LDSR + 2 * lk]) = pre[4 + q];
        }
    };

    gload(s0);
    sstore(0);
    __syncthreads();

    for (int st = s0; st < s1; st++) {
        const int b = (st - s0) & 1;
        if (st + 1 < s1) gload(st + 1);   // prefetch next stage into regs

        const float* Ap = As[b];
        const float* Bp = Bs[b];
#pragma unroll
        for (int kp = 0; kp < KB / 2; kp++) {
            unsigned long long af[4], bf[4];
#pragma unroll
            for (int ii = 0; ii < 4; ii++)
                af[ii] = *(const unsigned long long*)(Ap + (ty + 16 * ii) * LDSR + 2 * kp);
#pragma unroll
            for (int jj = 0; jj < 4; jj++)
                bf[jj] = *(const unsigned long long*)(Bp + (tx + 16 * jj) * LDSR + 2 * kp);
#pragma unroll
            for (int ii = 0; ii < 4; ii++)
#pragma unroll
                for (int jj = 0; jj < 4; jj++)
                    ffma2(acc[ii * 4 + jj], af[ii], bf[jj]);
        }

        if (st + 1 < s1) sstore(b ^ 1);
        __syncthreads();
    }

    float* __restrict__ R = d_Rp[s];
#pragma unroll
    for (int ii = 0; ii < 4; ii++)
#pragma unroll
        for (int jj = 0; jj < 4; jj++) {
            const unsigned long long u = acc[ii * 4 + jj];
            const float r = __uint_as_float((unsigned)u) +
                            __uint_as_float((unsigned)(u >> 32));
            const int gi = it * TILE + ty + 16 * ii;
            const int gj = jt * TILE + tx + 16 * jj;
            R[gi * BDIM + gj] = r;
            if (it != jt) R[gj * BDIM + gi] = r;
        }
}

// ---------------------------------------------------------------------------
// Kernel 2: merge the 29 slices into d_G. 64 blocks x 256 threads, one
// float4 per thread, 29 independent L2-hot loads each. Also zeroes *out.
// ---------------------------------------------------------------------------
__global__ void __launch_bounds__(256) merge_kernel(float* __restrict__ out) {
    const int idx = blockIdx.x * 256 + threadIdx.x;   // float4 index
    float4 v = make_float4(0.f, 0.f, 0.f, 0.f);
#pragma unroll
    for (int s = 0; s < NSLICE; s++) {
        const float4 p = *(const float4*)(&d_Rp[s][idx * 4]);
        v.x += p.x; v.y += p.y; v.z += p.z; v.w += p.w;
    }
    *(float4*)(&d_G[idx * 4]) = v;
    if (idx == 0) *out = 0.f;   // d_out is poisoned each replay
}

// ---------------------------------------------------------------------------
// Kernel 3: centering/normalization corrections + masked min/max + sum.
// 32 blocks x 256 threads, one warp per row; all reads L2-hot.
// ---------------------------------------------------------------------------
__global__ void __launch_bounds__(256) reduce_kernel(const int* __restrict__ tg,
                                                     float* __restrict__ out) {
    __shared__ int mlist[BDIM];
    __shared__ int mcount;
    __shared__ float su[BDIM];
    __shared__ float sinv[BDIM];

    const int tid = threadIdx.x;
    if (tid == 0) mcount = 0;
    __syncthreads();
    const int t_last = tg[BDIM - 4];   // targets[::4][-1]
    if (tg[tid] == t_last) {
        int p = atomicAdd(&mcount, 1);
        mlist[p] = tid;
    }
    __syncthreads();
    const int cnt = mcount;
    const float invc = 1.f / (float)cnt;

    float u = 0.f;
    for (int m = 0; m < cnt; m++) u += d_G[mlist[m] * BDIM + tid];
    u *= invc;
    su[tid] = u;
    const float dg = d_G[tid * (BDIM + 1)];
    __syncthreads();

    float cc = 0.f;
    for (int m = 0; m < cnt; m++) cc += su[mlist[m]];
    cc *= invc;

    const float wii = dg - 2.f * u + cc;   // ||x_tid - c||^2
    sinv[tid] = 1.f / fmaxf(sqrtf(fmaxf(wii, 0.f)), EPSN);
    __syncthreads();

    const int row = blockIdx.x * 8 + (tid >> 5);
    const int lane = tid & 31;
    const int trow = tg[row];
    const float ui = su[row];
    const float invi = sinv[row];
    const float INF = __int_as_float(0x7f800000);

    float pos = INF;
    float neg = 0.f;
#pragma unroll
    for (int jj = 0; jj < 8; jj++) {
        const int j = lane + 32 * jj;
        const float w = d_G[row * BDIM + j] - ui - su[j] + cc;
        const float ang = w * invi * sinv[j];
        const bool same = (tg[j] == trow);
        pos = fminf(pos, same ? ang : INF);
        neg = fmaxf(neg, same ? 0.f : fmaxf(ang, 0.f));
    }
#pragma unroll
    for (int o = 16; o; o >>= 1) {
        pos = fminf(pos, __shfl_xor_sync(0xffffffffu, pos, o));
        neg = fmaxf(neg, __shfl_xor_sync(0xffffffffu, neg, o));
    }
    if (lane == 0) atomicAdd(out, expf(neg - pos) * (1.f / 448.f));
}

// ---------------------------------------------------------------------------
extern "C" void kernel_launch(void* const* d_in, const int* in_sizes, int n_in,
                              void* d_out, int out_size) {
    const float* x  = (const float*)d_in[0];   // inputs  [256, 2048] fp32
    const int*   tg = (const int*)d_in[1];     // targets [256] int32
    // d_in[2] (subs) is unused by the reference math.
    float* out = (float*)d_out;                // scalar fp32

    gemm_kernel<<<dim3(NPAIR, NSLICE), 256>>>(x);
    merge_kernel<<<BDIM * BDIM / 4 / 256, 256>>>(out);
    reduce_kernel<<<BDIM / 8, 256>>>(tg, out);
}

// round 15
// speedup vs baseline: 1.0107x; 1.0091x over previous
#include <cuda_runtime.h>
#include <math.h>

// B=256 rows, C=2048 features, target groups of 4; output = LAST center's loss.
// Identity: with c = mean of matching rows and R = X X^T,
//   (x_i-c)·(x_j-c) = R_ij - u_i - u_j + cc,  u_i = mean_m R[m,i], cc = mean_m u_m
// so the GEMM runs on RAW inputs; centering/normalization is O(B^2) epilogue.
#define BDIM 256
#define CDIM 2048
#define KB 32                 // k's per smem stage
#define TOTSTG (CDIM / KB)    // 64 stages
#define NSLICE 29             // split-K slices -> 10*29 = 290 CTAs ~ 2/SM, 1 wave
#define NPAIR 10              // upper-triangle 64x64 tile pairs
#define TILE 64
#define LDSR 34               // padded smem row stride: conflict-free LDS.64
#define EPSN 1e-12f

// Scratch (no allocations allowed): per-slice partial Grams + merged Gram.
__device__ float d_Rp[NSLICE][BDIM * BDIM];  // 29 * 256 KB = 7.4 MB
__device__ float d_G[BDIM * BDIM];           // 256 KB

__device__ const int PIT[NPAIR] = {0, 0, 0, 0, 1, 1, 1, 2, 2, 3};
__device__ const int PJT[NPAIR] = {0, 1, 2, 3, 1, 2, 3, 2, 3, 3};

// Packed fp32x2 FMA (sm_10x): 2 fp32 FMA per issue slot on the fma pipe.
__device__ __forceinline__ void ffma2(unsigned long long& d,
                                      unsigned long long a,
                                      unsigned long long b) {
    asm("fma.rn.f32x2 %0, %1, %2, %0;" : "+l"(d) : "l"(a), "l"(b));
}

// ---------------------------------------------------------------------------
// Kernel 1: split-K Gram GEMM on raw X. Grid (NPAIR, NSLICE), 256 threads,
// 2 CTAs/SM. 64x64 tile, 4x4 micro-tile, fp32x2 k-parity accumulators,
// double-buffered smem with register prefetch. Plain STG epilogue into the
// slice's private buffer (+ mirror for off-diagonal tiles).
// ---------------------------------------------------------------------------
__global__ void __launch_bounds__(256, 2) gemm_kernel(const float* __restrict__ x) {
    __shared__ __align__(16) float As[2][TILE * LDSR];
    __shared__ __align__(16) float Bs[2][TILE * LDSR];

    const int tid = threadIdx.x;
    const int tx = tid & 15;       // j-lane (4 j's, strided 16)
    const int ty = tid >> 4;       // i-lane (4 i's, strided 16)
    const int it = PIT[blockIdx.x];
    const int jt = PJT[blockIdx.x];
    const int s  = blockIdx.y;
    const int s0 = (s * TOTSTG) / NSLICE;
    const int s1 = ((s + 1) * TOTSTG) / NSLICE;

    const int lr = tid >> 4;       // loader row-within-16
    const int lk = tid & 15;       // loader k-pair index

    float2 pre[8];
    unsigned long long acc[16];
#pragma unroll
    for (int i = 0; i < 16; i++) acc[i] = 0ull;

    // Stage loader: 64 rows x 32 k per tile = 1024 float2, 4 per thread.
    auto gload = [&](int st) {
        const int kb = st * KB + 2 * lk;
#pragma unroll
        for (int q = 0; q < 4; q++) {
            pre[q]     = *(const float2*)(x + (it * TILE + lr + 16 * q) * CDIM + kb);
            pre[4 + q] = *(const float2*)(x + (jt * TILE + lr + 16 * q) * CDIM + kb);
        }
    };
    auto sstore = [&](int b) {
#pragma unroll
        for (int q = 0; q < 4; q++) {
            *(float2*)(&As[b][(lr + 16 * q) * LDSR + 2 * lk]) = pre[q];
            *(float2*)(&Bs[b][(lr + 16 * q) * LDSR + 2 * lk]) = pre[4 + q];
        }
    };

    gload(s0);
    sstore(0);
    __syncthreads();

    for (int st = s0; st < s1; st++) {
        const int b = (st - s0) & 1;
        if (st + 1 < s1) gload(st + 1);   // prefetch next stage into regs

        const float* Ap = As[b];
        const float* Bp = Bs[b];
#pragma unroll
        for (int kp = 0; kp < KB / 2; kp++) {
            unsigned long long af[4], bf[4];
#pragma unroll
            for (int ii = 0; ii < 4; ii++)
                af[ii] = *(const unsigned long long*)(Ap + (ty + 16 * ii) * LDSR + 2 * kp);
#pragma unroll
            for (int jj = 0; jj < 4; jj++)
                bf[jj] = *(const unsigned long long*)(Bp + (tx + 16 * jj) * LDSR + 2 * kp);
#pragma unroll
            for (int ii = 0; ii < 4; ii++)
#pragma unroll
                for (int jj = 0; jj < 4; jj++)
                    ffma2(acc[ii * 4 + jj], af[ii], bf[jj]);
        }

        if (st + 1 < s1) sstore(b ^ 1);
        __syncthreads();
    }

    float* __restrict__ R = d_Rp[s];
#pragma unroll
    for (int ii = 0; ii < 4; ii++)
#pragma unroll
        for (int jj = 0; jj < 4; jj++) {
            const unsigned long long u = acc[ii * 4 + jj];
            const float r = __uint_as_float((unsigned)u) +
                            __uint_as_float((unsigned)(u >> 32));
            const int gi = it * TILE + ty + 16 * ii;
            const int gj = jt * TILE + tx + 16 * jj;
            R[gi * BDIM + gj] = r;
            if (it != jt) R[gj * BDIM + gi] = r;
        }
}

// ---------------------------------------------------------------------------
// Kernel 2: merge the 29 slices into d_G. 64 blocks x 256 threads, one
// float4 per thread, 29 independent L2-hot loads each. Also zeroes *out.
// ---------------------------------------------------------------------------
__global__ void __launch_bounds__(256) merge_kernel(float* __restrict__ out) {
    const int idx = blockIdx.x * 256 + threadIdx.x;   // float4 index
    float4 v = make_float4(0.f, 0.f, 0.f, 0.f);
#pragma unroll
    for (int s = 0; s < NSLICE; s++) {
        const float4 p = *(const float4*)(&d_Rp[s][idx * 4]);
        v.x += p.x; v.y += p.y; v.z += p.z; v.w += p.w;
    }
    *(float4*)(&d_G[idx * 4]) = v;
    if (idx == 0) *out = 0.f;   // d_out is poisoned each replay
}

// ---------------------------------------------------------------------------
// Kernel 3: centering/normalization corrections + masked min/max + sum.
// 32 blocks x 256 threads, one warp per row; all reads L2-hot.
// ---------------------------------------------------------------------------
__global__ void __launch_bounds__(256) reduce_kernel(const int* __restrict__ tg,
                                                     float* __restrict__ out) {
    __shared__ int mlist[BDIM];
    __shared__ int mcount;
    __shared__ float su[BDIM];
    __shared__ float sinv[BDIM];

    const int tid = threadIdx.x;
    if (tid == 0) mcount = 0;
    __syncthreads();
    const int t_last = tg[BDIM - 4];   // targets[::4][-1]
    if (tg[tid] == t_last) {
        int p = atomicAdd(&mcount, 1);
        mlist[p] = tid;
    }
    __syncthreads();
    const int cnt = mcount;
    const float invc = 1.f / (float)cnt;

    float u = 0.f;
    for (int m = 0; m < cnt; m++) u += d_G[mlist[m] * BDIM + tid];
    u *= invc;
    su[tid] = u;
    const float dg = d_G[tid * (BDIM + 1)];
    __syncthreads();

    float cc = 0.f;
    for (int m = 0; m < cnt; m++) cc += su[mlist[m]];
    cc *= invc;

    const float wii = dg - 2.f * u + cc;   // ||x_tid - c||^2
    sinv[tid] = 1.f / fmaxf(sqrtf(fmaxf(wii, 0.f)), EPSN);
    __syncthreads();

    const int row = blockIdx.x * 8 + (tid >> 5);
    const int lane = tid & 31;
    const int trow = tg[row];
    const float ui = su[row];
    const float invi = sinv[row];
    const float INF = __int_as_float(0x7f800000);

    float pos = INF;
    float neg = 0.f;
#pragma unroll
    for (int jj = 0; jj < 8; jj++) {
        const int j = lane + 32 * jj;
        const float w = d_G[row * BDIM + j] - ui - su[j] + cc;
        const float ang = w * invi * sinv[j];
        const bool same = (tg[j] == trow);
        pos = fminf(pos, same ? ang : INF);
        neg = fmaxf(neg, same ? 0.f : fmaxf(ang, 0.f));
    }
#pragma unroll
    for (int o = 16; o; o >>= 1) {
        pos = fminf(pos, __shfl_xor_sync(0xffffffffu, pos, o));
        neg = fmaxf(neg, __shfl_xor_sync(0xffffffffu, neg, o));
    }
    if (lane == 0) atomicAdd(out, expf(neg - pos) * (1.f / 448.f));
}

// ---------------------------------------------------------------------------
extern "C" void kernel_launch(void* const* d_in, const int* in_sizes, int n_in,
                              void* d_out, int out_size) {
    const float* x  = (const float*)d_in[0];   // inputs  [256, 2048] fp32
    const int*   tg = (const int*)d_in[1];     // targets [256] int32
    // d_in[2] (subs) is unused by the reference math.
    float* out = (float*)d_out;                // scalar fp32

    gemm_kernel<<<dim3(NPAIR, NSLICE), 256>>>(x);
    merge_kernel<<<BDIM * BDIM / 4 / 256, 256>>>(out);
    reduce_kernel<<<BDIM / 8, 256>>>(tg, out);
}

// round 16
// speedup vs baseline: 1.0122x; 1.0015x over previous
#include <cuda_runtime.h>
#include <math.h>

// B=256 rows, C=2048 features, target groups of 4; output = LAST center's loss.
// Identity: with c = mean of matching rows and R = X X^T,
//   (x_i-c)·(x_j-c) = R_ij - u_i - u_j + cc,  u_i = mean_m R[m,i], cc = mean_m u_m
// so the GEMM runs on RAW inputs; centering/normalization is O(B^2) epilogue.
#define BDIM 256
#define CDIM 2048
#define KB 32                 // k's per smem stage
#define TOTSTG (CDIM / KB)    // 64 stages
#define NSLICE 29             // split-K slices -> 10*29 = 290 CTAs ~ 2/SM, 1 wave
#define NPAIR 10              // upper-triangle 64x64 tile pairs
#define TILE 64
#define LDSR 34               // padded smem row stride: conflict-free LDS.64
#define EPSN 1e-12f

// Scratch (no allocations allowed): per-slice partial Grams + merged Gram.
__device__ float d_Rp[NSLICE][BDIM * BDIM];  // 29 * 256 KB = 7.4 MB
__device__ float d_G[BDIM * BDIM];           // 256 KB

__device__ const int PIT[NPAIR] = {0, 0, 0, 0, 1, 1, 1, 2, 2, 3};
__device__ const int PJT[NPAIR] = {0, 1, 2, 3, 1, 2, 3, 2, 3, 3};

// Packed fp32x2 FMA (sm_10x): 2 fp32 FMA per issue slot on the fma pipe.
__device__ __forceinline__ void ffma2(unsigned long long& d,
                                      unsigned long long a,
                                      unsigned long long b) {
    asm("fma.rn.f32x2 %0, %1, %2, %0;" : "+l"(d) : "l"(a), "l"(b));
}

// ---------------------------------------------------------------------------
// Kernel 1: split-K Gram GEMM on raw X. Grid (NPAIR, NSLICE), 256 threads,
// 2 CTAs/SM. 64x64 tile, 4x4 micro-tile, fp32x2 k-parity accumulators,
// double-buffered smem with register prefetch. Plain STG epilogue into the
// slice's private buffer (+ mirror for off-diagonal tiles).
// ---------------------------------------------------------------------------
__global__ void __launch_bounds__(256, 2) gemm_kernel(const float* __restrict__ x) {
    __shared__ __align__(16) float As[2][TILE * LDSR];
    __shared__ __align__(16) float Bs[2][TILE * LDSR];

    const int tid = threadIdx.x;
    const int tx = tid & 15;       // j-lane (4 j's, strided 16)
    const int ty = tid >> 4;       // i-lane (4 i's, strided 16)
    const int it = PIT[blockIdx.x];
    const int jt = PJT[blockIdx.x];
    const int s  = blockIdx.y;
    const int s0 = (s * TOTSTG) / NSLICE;
    const int s1 = ((s + 1) * TOTSTG) / NSLICE;

    const int lr = tid >> 4;       // loader row-within-16
    const int lk = tid & 15;       // loader k-pair index

    float2 pre[8];
    unsigned long long acc[16];
#pragma unroll
    for (int i = 0; i < 16; i++) acc[i] = 0ull;

    // Stage loader: 64 rows x 32 k per tile = 1024 float2, 4 per thread.
    auto gload = [&](int st) {
        const int kb = st * KB + 2 * lk;
#pragma unroll
        for (int q = 0; q < 4; q++) {
            pre[q]     = *(const float2*)(x + (it * TILE + lr + 16 * q) * CDIM + kb);
            pre[4 + q] = *(const float2*)(x + (jt * TILE + lr + 16 * q) * CDIM + kb);
        }
    };
    auto sstore = [&](int b) {
#pragma unroll
        for (int q = 0; q < 4; q++) {
            *(float2*)(&As[b][(lr + 16 * q) * LDSR + 2 * lk]) = pre[q];
            *(float2*)(&Bs[b][(lr + 16 * q) * LDSR + 2 * lk]) = pre[4 + q];
        }
    };

    gload(s0);
    sstore(0);
    __syncthreads();

    for (int st = s0; st < s1; st++) {
        const int b = (st - s0) & 1;
        if (st + 1 < s1) gload(st + 1);   // prefetch next stage into regs

        const float* Ap = As[b];
        const float* Bp = Bs[b];
#pragma unroll
        for (int kp = 0; kp < KB / 2; kp++) {
            unsigned long long af[4], bf[4];
#pragma unroll
            for (int ii = 0; ii < 4; ii++)
                af[ii] = *(const unsigned long long*)(Ap + (ty + 16 * ii) * LDSR + 2 * kp);
#pragma unroll
            for (int jj = 0; jj < 4; jj++)
                bf[jj] = *(const unsigned long long*)(Bp + (tx + 16 * jj) * LDSR + 2 * kp);
#pragma unroll
            for (int ii = 0; ii < 4; ii++)
#pragma unroll
                for (int jj = 0; jj < 4; jj++)
                    ffma2(acc[ii * 4 + jj], af[ii], bf[jj]);
        }

        if (st + 1 < s1) sstore(b ^ 1);
        __syncthreads();
    }

    float* __restrict__ R = d_Rp[s];
#pragma unroll
    for (int ii = 0; ii < 4; ii++)
#pragma unroll
        for (int jj = 0; jj < 4; jj++) {
            const unsigned long long u = acc[ii * 4 + jj];
            const float r = __uint_as_float((unsigned)u) +
                            __uint_as_float((unsigned)(u >> 32));
            const int gi = it * TILE + ty + 16 * ii;
            const int gj = jt * TILE + tx + 16 * jj;
            R[gi * BDIM + gj] = r;
            if (it != jt) R[gj * BDIM + gi] = r;
        }
}

// ---------------------------------------------------------------------------
// Kernel 2: merge the 29 slices into d_G. 64 blocks x 256 threads, one
// float4 per thread, 29 independent L2-hot loads each. Also zeroes *out.
// ---------------------------------------------------------------------------
__global__ void __launch_bounds__(256) merge_kernel(float* __restrict__ out) {
    const int idx = blockIdx.x * 256 + threadIdx.x;   // float4 index
    float4 v = make_float4(0.f, 0.f, 0.f, 0.f);
#pragma unroll
    for (int s = 0; s < NSLICE; s++) {
        const float4 p = *(const float4*)(&d_Rp[s][idx * 4]);
        v.x += p.x; v.y += p.y; v.z += p.z; v.w += p.w;
    }
    *(float4*)(&d_G[idx * 4]) = v;
    if (idx == 0) *out = 0.f;   // d_out is poisoned each replay
}

// ---------------------------------------------------------------------------
// Kernel 3: centering/normalization corrections + masked min/max + sum.
// 32 blocks x 256 threads, one warp per row; all reads L2-hot.
// ---------------------------------------------------------------------------
__global__ void __launch_bounds__(256) reduce_kernel(const int* __restrict__ tg,
                                                     float* __restrict__ out) {
    __shared__ int mlist[BDIM];
    __shared__ int mcount;
    __shared__ float su[BDIM];
    __shared__ float sinv[BDIM];

    const int tid = threadIdx.x;
    if (tid == 0) mcount = 0;
    __syncthreads();
    const int t_last = tg[BDIM - 4];   // targets[::4][-1]
    if (tg[tid] == t_last) {
        int p = atomicAdd(&mcount, 1);
        mlist[p] = tid;
    }
    __syncthreads();
    const int cnt = mcount;
    const float invc = 1.f / (float)cnt;

    float u = 0.f;
    for (int m = 0; m < cnt; m++) u += d_G[mlist[m] * BDIM + tid];
    u *= invc;
    su[tid] = u;
    const float dg = d_G[tid * (BDIM + 1)];
    __syncthreads();

    float cc = 0.f;
    for (int m = 0; m < cnt; m++) cc += su[mlist[m]];
    cc *= invc;

    const float wii = dg - 2.f * u + cc;   // ||x_tid - c||^2
    sinv[tid] = 1.f / fmaxf(sqrtf(fmaxf(wii, 0.f)), EPSN);
    __syncthreads();

    const int row = blockIdx.x * 8 + (tid >> 5);
    const int lane = tid & 31;
    const int trow = tg[row];
    const float ui = su[row];
    const float invi = sinv[row];
    const float INF = __int_as_float(0x7f800000);

    float pos = INF;
    float neg = 0.f;
#pragma unroll
    for (int jj = 0; jj < 8; jj++) {
        const int j = lane + 32 * jj;
        const float w = d_G[row * BDIM + j] - ui - su[j] + cc;
        const float ang = w * invi * sinv[j];
        const bool same = (tg[j] == trow);
        pos = fminf(pos, same ? ang : INF);
        neg = fmaxf(neg, same ? 0.f : fmaxf(ang, 0.f));
    }
#pragma unroll
    for (int o = 16; o; o >>= 1) {
        pos = fminf(pos, __shfl_xor_sync(0xffffffffu, pos, o));
        neg = fmaxf(neg, __shfl_xor_sync(0xffffffffu, neg, o));
    }
    if (lane == 0) atomicAdd(out, expf(neg - pos) * (1.f / 448.f));
}

// ---------------------------------------------------------------------------
extern "C" void kernel_launch(void* const* d_in, const int* in_sizes, int n_in,
                              void* d_out, int out_size) {
    const float* x  = (const float*)d_in[0];   // inputs  [256, 2048] fp32
    const int*   tg = (const int*)d_in[1];     // targets [256] int32
    // d_in[2] (subs) is unused by the reference math.
    float* out = (float*)d_out;                // scalar fp32

    gemm_kernel<<<dim3(NPAIR, NSLICE), 256>>>(x);
    merge_kernel<<<BDIM * BDIM / 4 / 256, 256>>>(out);
    reduce_kernel<<<BDIM / 8, 256>>>(tg, out);
}